// round 5
// baseline (speedup 1.0000x reference)
#include <cuda_runtime.h>
#include <cuda_fp16.h>

#define NN 20000
#define NE 640000
#define F  128
#define UN 16                     // nodes per tile in MLP kernel (20000 % 16 == 0)
#define NGROUPS (NN / UN)         // 1250
#define MLP_DSMEM (65536 + 16384) // Wsp pairs 64KB + duplicated input tile 16KB

// ---------------- scratch (device globals; no allocations allowed) ----------
__device__ __align__(16) float  g_agg[NN * F];   // aggregated (mean) features, f32
__device__ __align__(16) float  g_h[NN * F];     // layer-2 hidden, f32 (for k_final)
__device__ __align__(16) __half g_xh[NN * F];    // x in half (gather source L1)
__device__ __align__(16) __half g_hh[NN * F];    // h1 in half (gather source L2)
__device__ float g_inv[NN];       // 1 / max(indegree, 1)
__device__ int   g_cnt[NN];
__device__ int   g_off[NN + 1];   // CSR offsets by dst
__device__ int   g_cur[NN];       // fill cursors
__device__ int   g_esrc[NE];      // src ids grouped by dst
__device__ int   g_is64;          // 1 if edge_index is int64, 0 if int32

// ---------------- packed f32x2 helpers ---------------------------------------
__device__ __forceinline__ unsigned long long ffma2(unsigned long long a,
                                                    unsigned long long b,
                                                    unsigned long long c) {
    unsigned long long d;
    asm("fma.rn.f32x2 %0, %1, %2, %3;" : "=l"(d) : "l"(a), "l"(b), "l"(c));
    return d;
}
__device__ __forceinline__ void unpack2(unsigned long long p, float& lo, float& hi) {
    asm("mov.b64 {%0, %1}, %2;" : "=f"(lo), "=f"(hi) : "l"(p));
}

// ---------------- prep: zero counters + dtype detect -------------------------
// int64 node ids < 2^31 have zero high words at odd int32 indices.
__global__ void k_prep(const int* __restrict__ ei32) {
    int i = blockIdx.x * blockDim.x + threadIdx.x;
    if (i < NN) g_cnt[i] = 0;
    if (i < 32) {
        int v = 0;
#pragma unroll
        for (int j = 0; j < 4; ++j) v |= ei32[2 * (i + 32 * j) + 1];
#pragma unroll
        for (int d = 16; d; d >>= 1) v |= __shfl_xor_sync(0xffffffffu, v, d);
        if (i == 0) g_is64 = (v == 0) ? 1 : 0;
    }
}

// ---------------- convert x -> half ------------------------------------------
__global__ void k_tohalf(const float4* __restrict__ x) {
    int i = blockIdx.x * blockDim.x + threadIdx.x;   // one float4 -> 2x half2
    if (i < NN * F / 4) {
        float4 v = x[i];
        __half2* o = (__half2*)g_xh;
        o[2 * i + 0] = __floats2half2_rn(v.x, v.y);
        o[2 * i + 1] = __floats2half2_rn(v.z, v.w);
    }
}

// ---------------- CSR build: 4 edges per thread -------------------------------
__global__ void k_count(const void* __restrict__ ei) {
    int t = blockIdx.x * blockDim.x + threadIdx.x;
    if (t >= NE / 4) return;
    int d0, d1, d2, d3;
    if (g_is64) {
        const longlong2* p = (const longlong2*)ei;
        longlong2 a = p[(NE + 4 * t) / 2], b = p[(NE + 4 * t) / 2 + 1];
        d0 = (int)a.x; d1 = (int)a.y; d2 = (int)b.x; d3 = (int)b.y;
    } else {
        int4 a = ((const int4*)ei)[(NE + 4 * t) / 4];
        d0 = a.x; d1 = a.y; d2 = a.z; d3 = a.w;
    }
    if ((unsigned)d0 < NN) atomicAdd(&g_cnt[d0], 1);
    if ((unsigned)d1 < NN) atomicAdd(&g_cnt[d1], 1);
    if ((unsigned)d2 < NN) atomicAdd(&g_cnt[d2], 1);
    if ((unsigned)d3 < NN) atomicAdd(&g_cnt[d3], 1);
}

// single-block coarsened scan: each of 1024 threads scans 20 elements in regs.
__global__ void k_scan() {
    __shared__ int wsum[32];
    int tid = threadIdx.x, lane = tid & 31, wid = tid >> 5;
    int base = tid * 20;
    int v[20];
    int run = 0;
#pragma unroll
    for (int j = 0; j < 20; ++j) {
        int i = base + j;
        int c = (i < NN) ? g_cnt[i] : 0;
        run += c;
        v[j] = run;                         // inclusive within thread
    }
    int s = run;
#pragma unroll
    for (int d = 1; d < 32; d <<= 1) {
        int t = __shfl_up_sync(0xffffffffu, s, d);
        if (lane >= d) s += t;
    }
    if (lane == 31) wsum[wid] = s;
    __syncthreads();
    if (wid == 0) {
        int ws = wsum[lane];
#pragma unroll
        for (int d = 1; d < 32; d <<= 1) {
            int t = __shfl_up_sync(0xffffffffu, ws, d);
            if (lane >= d) ws += t;
        }
        wsum[lane] = ws;
    }
    __syncthreads();
    int excl = (s - run) + (wid ? wsum[wid - 1] : 0);   // exclusive thread base
    if (tid == 0) g_off[0] = 0;
#pragma unroll
    for (int j = 0; j < 20; ++j) {
        int i = base + j;
        if (i < NN) {
            int inc = excl + v[j];
            int cnt = v[j] - (j ? v[j - 1] : 0);
            g_off[i + 1] = inc;
            g_cur[i]     = inc - cnt;
            g_inv[i]     = 1.0f / (float)(cnt > 0 ? cnt : 1);
        }
    }
}

__global__ void k_fill(const void* __restrict__ ei) {
    int t = blockIdx.x * blockDim.x + threadIdx.x;
    if (t >= NE / 4) return;
    int s0, s1, s2, s3, d0, d1, d2, d3;
    if (g_is64) {
        const longlong2* p = (const longlong2*)ei;
        longlong2 a = p[(4 * t) / 2],       b = p[(4 * t) / 2 + 1];
        longlong2 c = p[(NE + 4 * t) / 2],  d = p[(NE + 4 * t) / 2 + 1];
        s0 = (int)a.x; s1 = (int)a.y; s2 = (int)b.x; s3 = (int)b.y;
        d0 = (int)c.x; d1 = (int)c.y; d2 = (int)d.x; d3 = (int)d.y;
    } else {
        int4 a = ((const int4*)ei)[t];
        int4 c = ((const int4*)ei)[(NE + 4 * t) / 4];
        s0 = a.x; s1 = a.y; s2 = a.z; s3 = a.w;
        d0 = c.x; d1 = c.y; d2 = c.z; d3 = c.w;
    }
    if ((unsigned)d0 < NN && (unsigned)s0 < NN) g_esrc[atomicAdd(&g_cur[d0], 1)] = s0;
    if ((unsigned)d1 < NN && (unsigned)s1 < NN) g_esrc[atomicAdd(&g_cur[d1], 1)] = s1;
    if ((unsigned)d2 < NN && (unsigned)s2 < NN) g_esrc[atomicAdd(&g_cur[d2], 1)] = s2;
    if ((unsigned)d3 < NN && (unsigned)s3 < NN) g_esrc[atomicAdd(&g_cur[d3], 1)] = s3;
}

// ---------------- mean aggregation: one warp per dst node --------------------
// Gathers HALF rows (256B = 2 L2 lines per edge), accumulates f32 -> g_agg f32.
__global__ void k_agg(int use_h) {
    int warp = (blockIdx.x * blockDim.x + threadIdx.x) >> 5;
    int lane = threadIdx.x & 31;
    if (warp >= NN) return;
    const uint2* __restrict__ feat = use_h ? (const uint2*)g_hh : (const uint2*)g_xh;
    int beg = g_off[warp], end = g_off[warp + 1];
    float4 acc = make_float4(0.f, 0.f, 0.f, 0.f);
    int e0 = beg;
    for (; e0 + 32 <= end; e0 += 32) {          // full chunks, no bounds checks
        int myid = g_esrc[e0 + lane];
#pragma unroll 8
        for (int j = 0; j < 32; ++j) {
            int s = __shfl_sync(0xffffffffu, myid, j);
            uint2 r = feat[s * 32 + lane];
            float2 a = __half22float2(*(__half2*)&r.x);
            float2 b = __half22float2(*(__half2*)&r.y);
            acc.x += a.x; acc.y += a.y; acc.z += b.x; acc.w += b.y;
        }
    }
    int n = end - e0;
    if (n) {
        int myid = (lane < n) ? g_esrc[e0 + lane] : 0;
        for (int j = 0; j < n; ++j) {
            int s = __shfl_sync(0xffffffffu, myid, j);
            uint2 r = feat[s * 32 + lane];
            float2 a = __half22float2(*(__half2*)&r.x);
            float2 b = __half22float2(*(__half2*)&r.y);
            acc.x += a.x; acc.y += a.y; acc.z += b.x; acc.w += b.y;
        }
    }
    float inv = g_inv[warp];
    acc.x *= inv; acc.y *= inv; acc.z *= inv; acc.w *= inv;
    ((float4*)g_agg)[warp * 32 + lane] = acc;
}

// ---------------- fused (g_agg @ W + b) -> relu, packed f32x2 FMA ------------
// Thread tid: jp = tid&63 owns column pair (jp, jp+64); nh = tid>>6 owns nodes
// nh*8..nh*8+7 of the 16-node tile. W staged as (jp, jp+64) float2 pairs;
// inputs staged duplicated ((v,v) pairs) so each fma.rn.f32x2 does 2 real FMAs.
// half_out: 1 -> store __half to g_hh (layer 1), 0 -> store f32 to g_h (layer 2).
__global__ void __launch_bounds__(128) k_mlp(const float* __restrict__ W,
                                             const float* __restrict__ b,
                                             int half_out) {
    extern __shared__ char dyn[];
    float2*             Wsp  = (float2*)dyn;                  // [k][jp] pairs, 64KB
    float4*             Insd = (float4*)(dyn + 65536);        // [u][2*k4{+1}] dup, 16KB
    unsigned long long* InsU = (unsigned long long*)Insd;
    int tid = threadIdx.x;
    int jp  = tid & 63;
    int u0  = (tid >> 6) * 8;

    for (int e = tid; e < F * 64; e += 128) {
        int k = e >> 6, j = e & 63;
        Wsp[e] = make_float2(W[k * F + j], W[k * F + j + 64]);
    }
    float bj0 = b[jp], bj1 = b[jp + 64];
    const unsigned long long* WsU = (const unsigned long long*)Wsp;

    const float4* __restrict__ in4 = (const float4*)g_agg;
    for (int g = blockIdx.x; g < NGROUPS; g += gridDim.x) {
        int n0 = g * UN;
        __syncthreads();   // Wsp ready (first iter) / Insd reuse (later iters)
        for (int i = tid; i < UN * 32; i += 128) {
            float4 v = in4[n0 * 32 + i];           // node u=(i>>5), k4=(i&31)
            int u = i >> 5, k4 = i & 31;
            Insd[u * 64 + 2 * k4 + 0] = make_float4(v.x, v.x, v.y, v.y);
            Insd[u * 64 + 2 * k4 + 1] = make_float4(v.z, v.z, v.w, v.w);
        }
        __syncthreads();

        unsigned long long ac[8];
#pragma unroll
        for (int u = 0; u < 8; ++u) ac[u] = 0ULL;

#pragma unroll 2
        for (int k4 = 0; k4 < 32; ++k4) {
            unsigned long long w0 = WsU[(4 * k4 + 0) * 64 + jp];
            unsigned long long w1 = WsU[(4 * k4 + 1) * 64 + jp];
            unsigned long long w2 = WsU[(4 * k4 + 2) * 64 + jp];
            unsigned long long w3 = WsU[(4 * k4 + 3) * 64 + jp];
#pragma unroll
            for (int u = 0; u < 8; ++u) {
                const unsigned long long* p = &InsU[((u0 + u) * 64 + 2 * k4) * 2];
                ulonglong2 A = *(const ulonglong2*)p;        // (vx,vx) (vy,vy)
                ulonglong2 B = *(const ulonglong2*)(p + 2);  // (vz,vz) (vw,vw)
                ac[u] = ffma2(A.x, w0, ac[u]);
                ac[u] = ffma2(A.y, w1, ac[u]);
                ac[u] = ffma2(B.x, w2, ac[u]);
                ac[u] = ffma2(B.y, w3, ac[u]);
            }
        }
#pragma unroll
        for (int u = 0; u < 8; ++u) {
            float lo, hi;
            unpack2(ac[u], lo, hi);
            float r0 = lo + bj0, r1 = hi + bj1;
            r0 = r0 > 0.f ? r0 : 0.f;
            r1 = r1 > 0.f ? r1 : 0.f;
            int node = n0 + u0 + u;
            if (half_out) {
                g_hh[node * F + jp]      = __float2half(r0);
                g_hh[node * F + jp + 64] = __float2half(r1);
            } else {
                g_h[node * F + jp]       = r0;
                g_h[node * F + jp + 64]  = r1;
            }
        }
    }
}

// ---------------- final projection 128 -> 2 ----------------------------------
__global__ void k_final(const float* __restrict__ W3, const float* __restrict__ b3,
                        float* __restrict__ out) {
    int warp = (blockIdx.x * blockDim.x + threadIdx.x) >> 5;
    int lane = threadIdx.x & 31;
    if (warp >= NN) return;
    float4 v = ((const float4*)g_h)[warp * 32 + lane];
    // W3 row-major [128][2]; lane covers k = 4*lane .. 4*lane+3
    float4 wa = ((const float4*)W3)[lane * 2 + 0]; // k0:{o0,o1}, k1:{o0,o1}
    float4 wb = ((const float4*)W3)[lane * 2 + 1]; // k2:{o0,o1}, k3:{o0,o1}
    float p0 = v.x * wa.x + v.y * wa.z + v.z * wb.x + v.w * wb.z;
    float p1 = v.x * wa.y + v.y * wa.w + v.z * wb.y + v.w * wb.w;
#pragma unroll
    for (int d = 16; d; d >>= 1) {
        p0 += __shfl_down_sync(0xffffffffu, p0, d);
        p1 += __shfl_down_sync(0xffffffffu, p1, d);
    }
    if (lane == 0) {
        out[warp * 2 + 0] = p0 + b3[0];
        out[warp * 2 + 1] = p1 + b3[1];
    }
}

// ---------------- launch -----------------------------------------------------
extern "C" void kernel_launch(void* const* d_in, const int* in_sizes, int n_in,
                              void* d_out, int out_size) {
    const float* x  = (const float*)d_in[0];
    const void*  ei = d_in[1];
    const float* W1 = (const float*)d_in[2];
    const float* b1 = (const float*)d_in[3];
    const float* W2 = (const float*)d_in[4];
    const float* b2 = (const float*)d_in[5];
    const float* W3 = (const float*)d_in[6];
    const float* b3 = (const float*)d_in[7];
    float* out = (float*)d_out;

    cudaFuncSetAttribute(k_mlp, cudaFuncAttributeMaxDynamicSharedMemorySize, MLP_DSMEM);

    const int TB = 256;
    k_prep<<<(NN + TB - 1) / TB, TB>>>((const int*)ei);
    k_tohalf<<<(NN * F / 4 + TB - 1) / TB, TB>>>((const float4*)x);
    k_count<<<(NE / 4 + TB - 1) / TB, TB>>>(ei);
    k_scan<<<1, 1024>>>();
    k_fill<<<(NE / 4 + TB - 1) / TB, TB>>>(ei);

    int agg_blocks = (NN * 32 + TB - 1) / TB;   // one warp per node

    // layer 1
    k_agg<<<agg_blocks, TB>>>(0);
    k_mlp<<<304, 128, MLP_DSMEM>>>(W1, b1, 1);
    // layer 2
    k_agg<<<agg_blocks, TB>>>(1);
    k_mlp<<<304, 128, MLP_DSMEM>>>(W2, b2, 0);
    // output projection
    k_final<<<agg_blocks, TB>>>(W3, b3, out);
}

// round 8
// speedup vs baseline: 1.2215x; 1.2215x over previous
#include <cuda_runtime.h>
#include <cuda_fp16.h>

#define NN 20000
#define NE 640000
#define F  128
#define UN 16                     // nodes per tile in MLP kernel (20000 % 16 == 0)
#define NGROUPS (NN / UN)         // 1250
#define MLP_DSMEM (65536 + 16384) // Wsp pairs 64KB + duplicated input tile 16KB
#define NB 160                    // scan blocks
#define CH 125                    // elements per scan block (160*125 = 20000)

// ---------------- scratch (device globals; no allocations allowed) ----------
__device__ __align__(16) float  g_agg[NN * F];   // aggregated (mean) features, f32
__device__ __align__(16) float  g_h[NN * F];     // layer-2 hidden, f32 (for k_final)
__device__ __align__(16) __half g_xh[NN * F];    // x in half (gather source L1)
__device__ __align__(16) __half g_hh[NN * F];    // h1 in half (gather source L2)
__device__ float g_inv[NN];       // 1 / max(indegree, 1)
__device__ int   g_cnt[NN];
__device__ int   g_off[NN + 1];   // CSR offsets by dst
__device__ int   g_cur[NN];       // fill cursors
__device__ int   g_esrc[NE];      // src ids grouped by dst
__device__ int   g_bsum[NB];      // per-block count sums
__device__ int   g_is64;          // 1 if edge_index is int64, 0 if int32

// ---------------- packed f32x2 helpers ---------------------------------------
__device__ __forceinline__ unsigned long long ffma2(unsigned long long a,
                                                    unsigned long long b,
                                                    unsigned long long c) {
    unsigned long long d;
    asm("fma.rn.f32x2 %0, %1, %2, %3;" : "=l"(d) : "l"(a), "l"(b), "l"(c));
    return d;
}
__device__ __forceinline__ void unpack2(unsigned long long p, float& lo, float& hi) {
    asm("mov.b64 {%0, %1}, %2;" : "=f"(lo), "=f"(hi) : "l"(p));
}

// ---------------- prep: x->half + zero counters + dtype detect ---------------
// int64 node ids < 2^31 have zero high words at odd int32 indices.
__global__ void k_prep(const int* __restrict__ ei32, const float4* __restrict__ x) {
    int i = blockIdx.x * blockDim.x + threadIdx.x;
    if (i < NN * F / 4) {
        float4 v = x[i];
        __half2* o = (__half2*)g_xh;
        o[2 * i + 0] = __floats2half2_rn(v.x, v.y);
        o[2 * i + 1] = __floats2half2_rn(v.z, v.w);
    }
    if (i < NN) g_cnt[i] = 0;
    if (i < 32) {
        int v = 0;
#pragma unroll
        for (int j = 0; j < 4; ++j) v |= ei32[2 * (i + 32 * j) + 1];
#pragma unroll
        for (int d = 16; d; d >>= 1) v |= __shfl_xor_sync(0xffffffffu, v, d);
        if (i == 0) g_is64 = (v == 0) ? 1 : 0;
    }
}

// ---------------- CSR build: 4 edges per thread -------------------------------
__global__ void k_count(const void* __restrict__ ei) {
    int t = blockIdx.x * blockDim.x + threadIdx.x;
    if (t >= NE / 4) return;
    int d0, d1, d2, d3;
    if (g_is64) {
        const longlong2* p = (const longlong2*)ei;
        longlong2 a = p[(NE + 4 * t) / 2], b = p[(NE + 4 * t) / 2 + 1];
        d0 = (int)a.x; d1 = (int)a.y; d2 = (int)b.x; d3 = (int)b.y;
    } else {
        int4 a = ((const int4*)ei)[(NE + 4 * t) / 4];
        d0 = a.x; d1 = a.y; d2 = a.z; d3 = a.w;
    }
    if ((unsigned)d0 < NN) atomicAdd(&g_cnt[d0], 1);
    if ((unsigned)d1 < NN) atomicAdd(&g_cnt[d1], 1);
    if ((unsigned)d2 < NN) atomicAdd(&g_cnt[d2], 1);
    if ((unsigned)d3 < NN) atomicAdd(&g_cnt[d3], 1);
}

// ---------------- hierarchical scan (grid=160, no single-CTA kernels) --------
// A: per-block sum of its 125-element chunk.
__global__ void __launch_bounds__(128) k_scanA() {
    int b = blockIdx.x, t = threadIdx.x, lane = t & 31, wid = t >> 5;
    __shared__ int ws[4];
    int c = (t < CH) ? g_cnt[b * CH + t] : 0;
#pragma unroll
    for (int d = 16; d; d >>= 1) c += __shfl_xor_sync(0xffffffffu, c, d);
    if (lane == 0) ws[wid] = c;
    __syncthreads();
    if (t == 0) g_bsum[b] = ws[0] + ws[1] + ws[2] + ws[3];
}

// B: block base = sum of earlier block sums; then scan own chunk, emit outputs.
__global__ void __launch_bounds__(192) k_scanB() {
    int b = blockIdx.x, t = threadIdx.x, lane = t & 31, wid = t >> 5;
    __shared__ int bs[6];
    __shared__ int wsum[4];
    int v = (t < b) ? g_bsum[t] : 0;      // b <= 159 < 192 threads
#pragma unroll
    for (int d = 16; d; d >>= 1) v += __shfl_xor_sync(0xffffffffu, v, d);
    if (lane == 0) bs[wid] = v;
    __syncthreads();
    int base = bs[0] + bs[1] + bs[2] + bs[3] + bs[4] + bs[5];

    int i = b * CH + t;
    int c = (t < CH) ? g_cnt[i] : 0;
    int s = c;
#pragma unroll
    for (int d = 1; d < 32; d <<= 1) {
        int u = __shfl_up_sync(0xffffffffu, s, d);
        if (lane >= d) s += u;
    }
    if (lane == 31 && wid < 4) wsum[wid] = s;
    __syncthreads();
    int off = base;
#pragma unroll
    for (int w = 0; w < 4; ++w) off += (w < wid) ? wsum[w] : 0;
    if (t < CH) {
        int inc = off + s;
        g_off[i + 1] = inc;
        g_cur[i]     = inc - c;
        g_inv[i]     = 1.0f / (float)(c > 0 ? c : 1);
    }
    if (b == 0 && t == 0) g_off[0] = 0;
}

__global__ void k_fill(const void* __restrict__ ei) {
    int t = blockIdx.x * blockDim.x + threadIdx.x;
    if (t >= NE / 4) return;
    int s0, s1, s2, s3, d0, d1, d2, d3;
    if (g_is64) {
        const longlong2* p = (const longlong2*)ei;
        longlong2 a = p[(4 * t) / 2],       b = p[(4 * t) / 2 + 1];
        longlong2 c = p[(NE + 4 * t) / 2],  d = p[(NE + 4 * t) / 2 + 1];
        s0 = (int)a.x; s1 = (int)a.y; s2 = (int)b.x; s3 = (int)b.y;
        d0 = (int)c.x; d1 = (int)c.y; d2 = (int)d.x; d3 = (int)d.y;
    } else {
        int4 a = ((const int4*)ei)[t];
        int4 c = ((const int4*)ei)[(NE + 4 * t) / 4];
        s0 = a.x; s1 = a.y; s2 = a.z; s3 = a.w;
        d0 = c.x; d1 = c.y; d2 = c.z; d3 = c.w;
    }
    if ((unsigned)d0 < NN && (unsigned)s0 < NN) g_esrc[atomicAdd(&g_cur[d0], 1)] = s0;
    if ((unsigned)d1 < NN && (unsigned)s1 < NN) g_esrc[atomicAdd(&g_cur[d1], 1)] = s1;
    if ((unsigned)d2 < NN && (unsigned)s2 < NN) g_esrc[atomicAdd(&g_cur[d2], 1)] = s2;
    if ((unsigned)d3 < NN && (unsigned)s3 < NN) g_esrc[atomicAdd(&g_cur[d3], 1)] = s3;
}

// ---------------- mean aggregation: one warp per dst node --------------------
// Gathers HALF rows (256B = 2 L2 lines per edge), accumulates f32 -> g_agg f32.
__global__ void k_agg(int use_h) {
    int warp = (blockIdx.x * blockDim.x + threadIdx.x) >> 5;
    int lane = threadIdx.x & 31;
    if (warp >= NN) return;
    const uint2* __restrict__ feat = use_h ? (const uint2*)g_hh : (const uint2*)g_xh;
    int beg = g_off[warp], end = g_off[warp + 1];
    float4 acc = make_float4(0.f, 0.f, 0.f, 0.f);
    int e0 = beg;
    for (; e0 + 32 <= end; e0 += 32) {          // full chunks, no bounds checks
        int myid = g_esrc[e0 + lane];
#pragma unroll 8
        for (int j = 0; j < 32; ++j) {
            int s = __shfl_sync(0xffffffffu, myid, j);
            uint2 r = feat[s * 32 + lane];
            float2 a = __half22float2(*(__half2*)&r.x);
            float2 b = __half22float2(*(__half2*)&r.y);
            acc.x += a.x; acc.y += a.y; acc.z += b.x; acc.w += b.y;
        }
    }
    int n = end - e0;
    if (n) {
        int myid = (lane < n) ? g_esrc[e0 + lane] : 0;
        for (int j = 0; j < n; ++j) {
            int s = __shfl_sync(0xffffffffu, myid, j);
            uint2 r = feat[s * 32 + lane];
            float2 a = __half22float2(*(__half2*)&r.x);
            float2 b = __half22float2(*(__half2*)&r.y);
            acc.x += a.x; acc.y += a.y; acc.z += b.x; acc.w += b.y;
        }
    }
    float inv = g_inv[warp];
    acc.x *= inv; acc.y *= inv; acc.z *= inv; acc.w *= inv;
    ((float4*)g_agg)[warp * 32 + lane] = acc;
}

// ---------------- fused (g_agg @ W + b) -> relu, packed f32x2 FMA ------------
__global__ void __launch_bounds__(128) k_mlp(const float* __restrict__ W,
                                             const float* __restrict__ b,
                                             int half_out) {
    extern __shared__ char dyn[];
    float2*             Wsp  = (float2*)dyn;                  // [k][jp] pairs, 64KB
    float4*             Insd = (float4*)(dyn + 65536);        // duplicated inputs, 16KB
    unsigned long long* InsU = (unsigned long long*)Insd;
    int tid = threadIdx.x;
    int jp  = tid & 63;
    int u0  = (tid >> 6) * 8;

    for (int e = tid; e < F * 64; e += 128) {
        int k = e >> 6, j = e & 63;
        Wsp[e] = make_float2(W[k * F + j], W[k * F + j + 64]);
    }
    float bj0 = b[jp], bj1 = b[jp + 64];
    const unsigned long long* WsU = (const unsigned long long*)Wsp;

    const float4* __restrict__ in4 = (const float4*)g_agg;
    for (int g = blockIdx.x; g < NGROUPS; g += gridDim.x) {
        int n0 = g * UN;
        __syncthreads();   // Wsp ready (first iter) / Insd reuse (later iters)
        for (int i = tid; i < UN * 32; i += 128) {
            float4 v = in4[n0 * 32 + i];           // node u=(i>>5), k4=(i&31)
            int u = i >> 5, k4 = i & 31;
            Insd[u * 64 + 2 * k4 + 0] = make_float4(v.x, v.x, v.y, v.y);
            Insd[u * 64 + 2 * k4 + 1] = make_float4(v.z, v.z, v.w, v.w);
        }
        __syncthreads();

        unsigned long long ac[8];
#pragma unroll
        for (int u = 0; u < 8; ++u) ac[u] = 0ULL;

#pragma unroll 2
        for (int k4 = 0; k4 < 32; ++k4) {
            unsigned long long w0 = WsU[(4 * k4 + 0) * 64 + jp];
            unsigned long long w1 = WsU[(4 * k4 + 1) * 64 + jp];
            unsigned long long w2 = WsU[(4 * k4 + 2) * 64 + jp];
            unsigned long long w3 = WsU[(4 * k4 + 3) * 64 + jp];
#pragma unroll
            for (int u = 0; u < 8; ++u) {
                const unsigned long long* p = &InsU[((u0 + u) * 64 + 2 * k4) * 2];
                ulonglong2 A = *(const ulonglong2*)p;        // (vx,vx) (vy,vy)
                ulonglong2 B = *(const ulonglong2*)(p + 2);  // (vz,vz) (vw,vw)
                ac[u] = ffma2(A.x, w0, ac[u]);
                ac[u] = ffma2(A.y, w1, ac[u]);
                ac[u] = ffma2(B.x, w2, ac[u]);
                ac[u] = ffma2(B.y, w3, ac[u]);
            }
        }
#pragma unroll
        for (int u = 0; u < 8; ++u) {
            float lo, hi;
            unpack2(ac[u], lo, hi);
            float r0 = lo + bj0, r1 = hi + bj1;
            r0 = r0 > 0.f ? r0 : 0.f;
            r1 = r1 > 0.f ? r1 : 0.f;
            int node = n0 + u0 + u;
            if (half_out) {
                g_hh[node * F + jp]      = __float2half(r0);
                g_hh[node * F + jp + 64] = __float2half(r1);
            } else {
                g_h[node * F + jp]       = r0;
                g_h[node * F + jp + 64]  = r1;
            }
        }
    }
}

// ---------------- final projection 128 -> 2 ----------------------------------
__global__ void k_final(const float* __restrict__ W3, const float* __restrict__ b3,
                        float* __restrict__ out) {
    int warp = (blockIdx.x * blockDim.x + threadIdx.x) >> 5;
    int lane = threadIdx.x & 31;
    if (warp >= NN) return;
    float4 v = ((const float4*)g_h)[warp * 32 + lane];
    float4 wa = ((const float4*)W3)[lane * 2 + 0]; // k0:{o0,o1}, k1:{o0,o1}
    float4 wb = ((const float4*)W3)[lane * 2 + 1]; // k2:{o0,o1}, k3:{o0,o1}
    float p0 = v.x * wa.x + v.y * wa.z + v.z * wb.x + v.w * wb.z;
    float p1 = v.x * wa.y + v.y * wa.w + v.z * wb.y + v.w * wb.w;
#pragma unroll
    for (int d = 16; d; d >>= 1) {
        p0 += __shfl_down_sync(0xffffffffu, p0, d);
        p1 += __shfl_down_sync(0xffffffffu, p1, d);
    }
    if (lane == 0) {
        out[warp * 2 + 0] = p0 + b3[0];
        out[warp * 2 + 1] = p1 + b3[1];
    }
}

// ---------------- launch -----------------------------------------------------
extern "C" void kernel_launch(void* const* d_in, const int* in_sizes, int n_in,
                              void* d_out, int out_size) {
    const float* x  = (const float*)d_in[0];
    const void*  ei = d_in[1];
    const float* W1 = (const float*)d_in[2];
    const float* b1 = (const float*)d_in[3];
    const float* W2 = (const float*)d_in[4];
    const float* b2 = (const float*)d_in[5];
    const float* W3 = (const float*)d_in[6];
    const float* b3 = (const float*)d_in[7];
    float* out = (float*)d_out;

    cudaFuncSetAttribute(k_mlp, cudaFuncAttributeMaxDynamicSharedMemorySize, MLP_DSMEM);

    const int TB = 256;
    k_prep<<<(NN * F / 4 + TB - 1) / TB, TB>>>((const int*)ei, (const float4*)x);
    k_count<<<(NE / 4 + TB - 1) / TB, TB>>>(ei);
    k_scanA<<<NB, 128>>>();
    k_scanB<<<NB, 192>>>();
    k_fill<<<(NE / 4 + TB - 1) / TB, TB>>>(ei);

    int agg_blocks = (NN * 32 + TB - 1) / TB;   // one warp per node

    // layer 1
    k_agg<<<agg_blocks, TB>>>(0);
    k_mlp<<<296, 128, MLP_DSMEM>>>(W1, b1, 1);
    // layer 2
    k_agg<<<agg_blocks, TB>>>(1);
    k_mlp<<<296, 128, MLP_DSMEM>>>(W2, b2, 0);
    // output projection
    k_final<<<agg_blocks, TB>>>(W3, b3, out);
}